// round 9
// baseline (speedup 1.0000x reference)
#include <cuda_runtime.h>
#include <cuda_bf16.h>
#include <math.h>

// Problem constants (fixed by the reference)
#define BB   4
#define HH   56
#define WW   56
#define Csz  192
#define Gsz  12
#define CG   16
#define Kpts 8
#define HID  768
#define HP   58
#define WP   58
#define NTOK (BB*HH*WW)          // 12544
#define PADSP (HP*WP)            // 3364
#define NOM  288                  // off(192) + mask(96) concatenated

// ---------------- scratch (device globals; no allocation) ----------------
__device__ float g_xln[NTOK*Csz];
__device__ float g_pad[BB*PADSP*Csz];      // padded value (in_proj output)
__device__ float g_x1 [NTOK*Csz];          // dwconv+LN+GELU (tf32-rounded)
__device__ float g_off[NTOK*Csz];          // G*K*2 = 192
__device__ float g_msk[NTOK*Gsz*Kpts];     // 96 logits
__device__ float g_dcn[NTOK*Csz];          // sampling output (tf32-rounded)
__device__ float g_d  [NTOK*Csz];          // out_proj output
__device__ float g_x2 [NTOK*Csz];          // x + LN(d)
__device__ float g_t  [NTOK*Csz];          // LN(x2, norm2) (tf32-rounded)
__device__ float g_h1 [NTOK*HID];          // (tf32-rounded)
__device__ float g_h2 [NTOK*Csz];
// tf32-rounded weight copies
__device__ float g_w1 [Csz*Csz];           // in_proj
__device__ float g_wom[Csz*NOM];           // off | mask concat
__device__ float g_bom[NOM];               // off_b | mask_b concat
__device__ float g_w2 [Csz*Csz];           // out_proj
__device__ float g_w3 [Csz*HID];           // fc1
__device__ float g_w4 [HID*Csz];           // fc2

// ---------------- helpers ----------------
__device__ __forceinline__ float gelu_exact(float x) {
    return 0.5f * x * (1.0f + erff(x * 0.70710678118654752f));
}

__device__ __forceinline__ float round_tf32(float x) {
    unsigned r;
    asm("cvt.rna.tf32.f32 %0, %1;" : "=r"(r) : "f"(x));
    return __uint_as_float(r);
}

__device__ __forceinline__ unsigned smem_u32(const void* p) {
    return (unsigned)__cvta_generic_to_shared(p);
}

__device__ __forceinline__ void cp_async16(unsigned dst, const void* src, int src_bytes) {
    asm volatile("cp.async.cg.shared.global [%0], [%1], 16, %2;"
                 :: "r"(dst), "l"(src), "r"(src_bytes));
}

// ---------------- setup work sizes ----------------
#define W1_SZ (Csz*Csz)
#define WOM_SZ (Csz*NOM)
#define W3_SZ (Csz*HID)
#define PREP_TOTAL (W1_SZ + WOM_SZ + W1_SZ + W3_SZ + W3_SZ + NOM)
#define BORDER_TOTAL (BB*228*Csz)
#define SETUP_TOTAL (PREP_TOTAL + BORDER_TOTAL)
#define SETUP_BLOCKS 684

__device__ __forceinline__ void setup_work(int i,
        const float* ipw, const float* offw, const float* maskw,
        const float* opw, const float* f1w, const float* f2w,
        const float* offb, const float* maskb) {
    int j = i;
    if (j < BORDER_TOTAL) {
        const int per_img = 228 * Csz;
        int b = j / per_img;
        int r = j % per_img;
        int cell = r / Csz, c = r % Csz;
        int h, w;
        if      (cell < 58)  { h = 0;              w = cell; }
        else if (cell < 116) { h = HP-1;           w = cell - 58; }
        else if (cell < 172) { h = cell - 116 + 1; w = 0; }
        else                 { h = cell - 172 + 1; w = WP-1; }
        g_pad[((size_t)b*PADSP + (size_t)h*WP + w)*Csz + c] = 0.f;
        return;
    }
    j -= BORDER_TOTAL;
    if (j < W1_SZ) { g_w1[j] = round_tf32(ipw[j]); return; }
    j -= W1_SZ;
    if (j < WOM_SZ) {
        int row = j / NOM, col = j % NOM;
        float v = (col < Csz) ? offw[row*(Gsz*Kpts*2) + col] : maskw[row*(Gsz*Kpts) + col - Csz];
        g_wom[j] = round_tf32(v);
        return;
    }
    j -= WOM_SZ;
    if (j < W1_SZ) { g_w2[j] = round_tf32(opw[j]); return; }
    j -= W1_SZ;
    if (j < W3_SZ) { g_w3[j] = round_tf32(f1w[j]); return; }
    j -= W3_SZ;
    if (j < W3_SZ) { g_w4[j] = round_tf32(f2w[j]); return; }
    j -= W3_SZ;
    g_bom[j] = (j < Csz) ? offb[j] : maskb[j - Csz];
}

// ---------------- fat kernel A: LN(x, norm1) -> xln (rounded)  +  setup ----
__global__ void lnsetup_kernel(const float* __restrict__ x,
                               const float* __restrict__ w, const float* __restrict__ b,
                               const float* __restrict__ ipw,
                               const float* __restrict__ offw, const float* __restrict__ maskw,
                               const float* __restrict__ opw,
                               const float* __restrict__ f1w, const float* __restrict__ f2w,
                               const float* __restrict__ offb, const float* __restrict__ maskb) {
    if (blockIdx.x >= NTOK) {
        int base = (blockIdx.x - NTOK) * blockDim.x + threadIdx.x;
        for (int i = base; i < SETUP_TOTAL; i += SETUP_BLOCKS * blockDim.x)
            setup_work(i, ipw, offw, maskw, opw, f1w, f2w, offb, maskb);
        return;
    }
    int n = blockIdx.x;
    int c = threadIdx.x;
    float v = x[n*Csz + c];
    float s = v, s2 = v*v;
    #pragma unroll
    for (int o = 16; o; o >>= 1) {
        s  += __shfl_xor_sync(0xffffffffu, s,  o);
        s2 += __shfl_xor_sync(0xffffffffu, s2, o);
    }
    __shared__ float red[12];
    int wid = c >> 5, lane = c & 31;
    if (lane == 0) { red[wid] = s; red[6+wid] = s2; }
    __syncthreads();
    if (c == 0) {
        float S = 0.f, S2 = 0.f;
        #pragma unroll
        for (int i = 0; i < 6; i++) { S += red[i]; S2 += red[6+i]; }
        red[0] = S; red[6] = S2;
    }
    __syncthreads();
    float mu  = red[0] * (1.0f/Csz);
    float var = red[6] * (1.0f/Csz) - mu*mu;
    g_xln[n*Csz + c] = round_tf32((v - mu) * rsqrtf(var + 1e-5f) * w[c] + b[c]);
}

// ---------------- generic LN kernel: out = LN(in)*w+b (+ res), opt rounding ----
__global__ void ln_kernel(const float* __restrict__ in, const float* __restrict__ res,
                          const float* __restrict__ w, const float* __restrict__ b,
                          float* __restrict__ out, float eps, int rnd) {
    int n = blockIdx.x;
    int c = threadIdx.x;
    float v = in[n*Csz + c];
    float s = v, s2 = v*v;
    #pragma unroll
    for (int o = 16; o; o >>= 1) {
        s  += __shfl_xor_sync(0xffffffffu, s,  o);
        s2 += __shfl_xor_sync(0xffffffffu, s2, o);
    }
    __shared__ float red[12];
    int wid = c >> 5, lane = c & 31;
    if (lane == 0) { red[wid] = s; red[6+wid] = s2; }
    __syncthreads();
    if (c == 0) {
        float S = 0.f, S2 = 0.f;
        #pragma unroll
        for (int i = 0; i < 6; i++) { S += red[i]; S2 += red[6+i]; }
        red[0] = S; red[6] = S2;
    }
    __syncthreads();
    float mu  = red[0] * (1.0f/Csz);
    float var = red[6] * (1.0f/Csz) - mu*mu;
    float o = (v - mu) * rsqrtf(var + eps) * w[c] + b[c];
    if (res) o += res[n*Csz + c];
    if (rnd) o = round_tf32(o);
    out[n*Csz + c] = o;
}

// ---------------- fused: x2 = x + LN(d, rpn1); t = round(LN(x2, norm2)) ----------------
__global__ void ln_fuse2_kernel(const float* __restrict__ d_in, const float* __restrict__ x_in,
                                const float* __restrict__ w1, const float* __restrict__ b1,
                                const float* __restrict__ w2, const float* __restrict__ b2,
                                float* __restrict__ x2_out, float* __restrict__ t_out) {
    int n = blockIdx.x;
    int c = threadIdx.x;
    __shared__ float red[12];
    int wid = c >> 5, lane = c & 31;

    float v = d_in[n*Csz + c];
    float s = v, s2 = v*v;
    #pragma unroll
    for (int o = 16; o; o >>= 1) {
        s  += __shfl_xor_sync(0xffffffffu, s,  o);
        s2 += __shfl_xor_sync(0xffffffffu, s2, o);
    }
    if (lane == 0) { red[wid] = s; red[6+wid] = s2; }
    __syncthreads();
    if (c == 0) {
        float S = 0.f, S2 = 0.f;
        #pragma unroll
        for (int i = 0; i < 6; i++) { S += red[i]; S2 += red[6+i]; }
        red[0] = S; red[6] = S2;
    }
    __syncthreads();
    float mu  = red[0] * (1.0f/Csz);
    float var = red[6] * (1.0f/Csz) - mu*mu;
    float x2 = x_in[n*Csz + c] + (v - mu) * rsqrtf(var + 1e-5f) * w1[c] + b1[c];
    x2_out[n*Csz + c] = x2;
    __syncthreads();   // red[] reuse

    s = x2; s2 = x2*x2;
    #pragma unroll
    for (int o = 16; o; o >>= 1) {
        s  += __shfl_xor_sync(0xffffffffu, s,  o);
        s2 += __shfl_xor_sync(0xffffffffu, s2, o);
    }
    if (lane == 0) { red[wid] = s; red[6+wid] = s2; }
    __syncthreads();
    if (c == 0) {
        float S = 0.f, S2 = 0.f;
        #pragma unroll
        for (int i = 0; i < 6; i++) { S += red[i]; S2 += red[6+i]; }
        red[0] = S; red[6] = S2;
    }
    __syncthreads();
    mu  = red[0] * (1.0f/Csz);
    var = red[6] * (1.0f/Csz) - mu*mu;
    t_out[n*Csz + c] = round_tf32((x2 - mu) * rsqrtf(var + 1e-5f) * w2[c] + b2[c]);
}

// ---------------- GEMM tile body (128x64, 2-stage cp.async, tf32) ----------
#define AS_STRIDE 20
#define BS_STRIDE 72
struct GemmSmem {
    float As[2][128*AS_STRIDE];
    float Bs[2][16*BS_STRIDE];
};

__device__ __forceinline__ void gemm_tile_body(
        GemmSmem* sm, const float* __restrict__ A, const float* __restrict__ W,
        const float* __restrict__ bias, float* __restrict__ C,
        int M, int N, int K, int row0, int col0, int act, int out_mode, int rnd) {
    int tid = threadIdx.x;
    int lane = tid & 31, warp = tid >> 5;
    int gid = lane >> 2, tig = lane & 3;
    int wr = (warp >> 1) * 32;
    int wc = (warp & 1) * 32;

    int a_row = tid >> 1;
    int a_k   = (tid & 1) * 8;
    int b_row = tid >> 4;
    int b_n   = (tid & 15) * 4;

    const float* Abase = A + (size_t)(row0 + a_row)*K + a_k;
    const float* Wbase = W + (size_t)b_row*N + col0 + b_n;
    int b_valid = (col0 + b_n + 4 <= N) ? 16 : 0;

    unsigned as_dst0 = smem_u32(&sm->As[0][a_row*AS_STRIDE + a_k]);
    unsigned as_dst1 = smem_u32(&sm->As[1][a_row*AS_STRIDE + a_k]);
    unsigned bs_dst0 = smem_u32(&sm->Bs[0][b_row*BS_STRIDE + b_n]);
    unsigned bs_dst1 = smem_u32(&sm->Bs[1][b_row*BS_STRIDE + b_n]);

    float acc[2][4][4];
    #pragma unroll
    for (int mi = 0; mi < 2; mi++)
        #pragma unroll
        for (int ni = 0; ni < 4; ni++)
            #pragma unroll
            for (int r = 0; r < 4; r++) acc[mi][ni][r] = 0.f;

    int stages = K / 16;

    cp_async16(as_dst0,      Abase,     16);
    cp_async16(as_dst0 + 16, Abase + 4, 16);
    cp_async16(bs_dst0, Wbase, b_valid);
    asm volatile("cp.async.commit_group;");

    for (int it = 0; it < stages; it++) {
        asm volatile("cp.async.wait_group 0;");
        __syncthreads();

        if (it + 1 < stages) {
            int k0n = (it + 1) * 16;
            const float* An = Abase + k0n;
            const float* Wn = Wbase + (size_t)k0n * N;
            unsigned ad = ((it + 1) & 1) ? as_dst1 : as_dst0;
            unsigned bd = ((it + 1) & 1) ? bs_dst1 : bs_dst0;
            cp_async16(ad,      An,     16);
            cp_async16(ad + 16, An + 4, 16);
            cp_async16(bd, Wn, b_valid);
            asm volatile("cp.async.commit_group;");
        }

        const unsigned* as = (const unsigned*)sm->As[it & 1];
        const unsigned* bs = (const unsigned*)sm->Bs[it & 1];
        #pragma unroll
        for (int ks = 0; ks < 2; ks++) {
            int kb = ks * 8;
            unsigned af[2][4], bf[4][2];
            #pragma unroll
            for (int mi = 0; mi < 2; mi++) {
                int mrow = wr + mi*16 + gid;
                af[mi][0] = as[ mrow   *AS_STRIDE + kb + tig    ];
                af[mi][1] = as[(mrow+8)*AS_STRIDE + kb + tig    ];
                af[mi][2] = as[ mrow   *AS_STRIDE + kb + tig + 4];
                af[mi][3] = as[(mrow+8)*AS_STRIDE + kb + tig + 4];
            }
            #pragma unroll
            for (int ni = 0; ni < 4; ni++) {
                int ncol = wc + ni*8 + gid;
                bf[ni][0] = bs[(kb + tig    )*BS_STRIDE + ncol];
                bf[ni][1] = bs[(kb + tig + 4)*BS_STRIDE + ncol];
            }
            #pragma unroll
            for (int mi = 0; mi < 2; mi++)
                #pragma unroll
                for (int ni = 0; ni < 4; ni++) {
                    asm volatile(
                        "mma.sync.aligned.m16n8k8.row.col.f32.tf32.tf32.f32 "
                        "{%0,%1,%2,%3}, {%4,%5,%6,%7}, {%8,%9}, {%0,%1,%2,%3};"
                        : "+f"(acc[mi][ni][0]), "+f"(acc[mi][ni][1]),
                          "+f"(acc[mi][ni][2]), "+f"(acc[mi][ni][3])
                        : "r"(af[mi][0]), "r"(af[mi][1]), "r"(af[mi][2]), "r"(af[mi][3]),
                          "r"(bf[ni][0]), "r"(bf[ni][1]));
                }
        }
        __syncthreads();
    }

    #pragma unroll
    for (int mi = 0; mi < 2; mi++) {
        #pragma unroll
        for (int ni = 0; ni < 4; ni++) {
            int r0 = row0 + wr + mi*16 + gid;
            int c0 = col0 + wc + ni*8 + 2*tig;
            #pragma unroll
            for (int rr = 0; rr < 2; rr++) {
                int row = r0 + rr*8;
                #pragma unroll
                for (int cc = 0; cc < 2; cc++) {
                    int col = c0 + cc;
                    if (col >= N) continue;
                    float v = acc[mi][ni][rr*2 + cc] + bias[col];
                    if (act == 1) v = gelu_exact(v);
                    if (rnd) v = round_tf32(v);
                    if (out_mode == 1) {
                        int bimg = row / (HH*WW);
                        int hw = row % (HH*WW);
                        int h = hw / WW, w = hw % WW;
                        g_pad[((size_t)bimg*PADSP + (size_t)(h+1)*WP + (w+1))*Csz + col] = v;
                    } else if (out_mode == 2) {
                        if (col < Csz) g_off[(size_t)row*Csz + col] = v;
                        else           g_msk[(size_t)row*(Gsz*Kpts) + col - Csz] = v;
                    } else {
                        C[(size_t)row*N + col] = v;
                    }
                }
            }
        }
    }
}

// ---------------- generic GEMM kernel ----------------
__global__ __launch_bounds__(256) void gemm_tf32_kernel(
        const float* __restrict__ A, const float* __restrict__ W,
        const float* __restrict__ bias, float* __restrict__ C,
        int M, int N, int K, int act, int out_mode, int rnd) {
    __shared__ GemmSmem sm;
    gemm_tile_body(&sm, A, W, bias, C, M, N, K, blockIdx.y*128, blockIdx.x*64,
                   act, out_mode, rnd);
}

// ---------------- fat kernel B: in_proj GEMM + depthwise conv ----------
#define GEMM_BLOCKS (3*(NTOK/128))        // 294
#define DW_BLOCKS   (BB*(HH/4)*WW)        // 3136
__global__ __launch_bounds__(256) void inproj_dw_kernel(
        const float* __restrict__ in_proj_b,
        const float* __restrict__ dww, const float* __restrict__ dwb,
        const float* __restrict__ lnw, const float* __restrict__ lnb) {
    __shared__ GemmSmem sm;   // dw path reuses the first bytes for its reduction
    if (blockIdx.x < GEMM_BLOCKS) {
        int gb = blockIdx.x;
        int col0 = (gb % 3) * 64;
        int row0 = (gb / 3) * 128;
        gemm_tile_body(&sm, g_xln, g_w1, in_proj_b, nullptr, NTOK, Csz, Csz,
                       row0, col0, 0, 1, 0);
        return;
    }
    // ---- dw path: 4 tokens (h0..h0+3, w) ----
    float* redS = (float*)&sm;            // 4*6 sums + 4*6 sqsums = 48 floats
    int blk = blockIdx.x - GEMM_BLOCKS;
    int bimg = blk / ((HH/4)*WW);
    int r = blk % ((HH/4)*WW);
    int h0 = (r / WW) * 4;
    int w = r % WW;
    int c = threadIdx.x;                  // only c < 192 active
    int wid = c >> 5, lane = c & 31;

    float accj[4] = {0.f, 0.f, 0.f, 0.f};
    float s[4], s2[4];
    if (c < Csz) {
        float wt[9];
        #pragma unroll
        for (int i = 0; i < 9; i++) wt[i] = dww[i*Csz + c];
        float vals[6][3];
        #pragma unroll
        for (int rr = 0; rr < 6; rr++) {
            int hh = h0 - 1 + rr;
            #pragma unroll
            for (int cc = 0; cc < 3; cc++) {
                int ww = w - 1 + cc;
                float v = 0.f;
                if (hh >= 0 && hh < HH && ww >= 0 && ww < WW)
                    v = g_xln[((bimg*HH + hh)*WW + ww)*Csz + c];
                vals[rr][cc] = v;
            }
        }
        float bc = dwb[c];
        #pragma unroll
        for (int j = 0; j < 4; j++) {
            float a = 0.f;
            #pragma unroll
            for (int ky = 0; ky < 3; ky++)
                #pragma unroll
                for (int kx = 0; kx < 3; kx++)
                    a += vals[j + ky][kx] * wt[ky*3 + kx];
            accj[j] = a + bc;
        }
        #pragma unroll
        for (int j = 0; j < 4; j++) { s[j] = accj[j]; s2[j] = accj[j]*accj[j]; }
        #pragma unroll
        for (int o = 16; o; o >>= 1) {
            #pragma unroll
            for (int j = 0; j < 4; j++) {
                s[j]  += __shfl_xor_sync(0xffffffffu, s[j],  o);
                s2[j] += __shfl_xor_sync(0xffffffffu, s2[j], o);
            }
        }
        if (lane == 0) {
            #pragma unroll
            for (int j = 0; j < 4; j++) {
                redS[j*6 + wid]      = s[j];
                redS[24 + j*6 + wid] = s2[j];
            }
        }
    }
    __syncthreads();
    if (c < Csz) {
        float lw = lnw[c], lb = lnb[c];
        #pragma unroll
        for (int j = 0; j < 4; j++) {
            float S = 0.f, S2 = 0.f;
            #pragma unroll
            for (int i = 0; i < 6; i++) { S += redS[j*6 + i]; S2 += redS[24 + j*6 + i]; }
            float mu  = S * (1.0f/Csz);
            float var = S2 * (1.0f/Csz) - mu*mu;
            float y = (accj[j] - mu) * rsqrtf(var + 1e-6f) * lw + lb;
            int n = (bimg*HH + h0 + j)*WW + w;
            g_x1[n*Csz + c] = round_tf32(gelu_exact(y));
        }
    }
}

// ---------------- DCNv3 sampling, two-phase (per-point precompute) ----------
// Phase 1 (96 threads, one per (g,k)): softmax weight, 4 clamped base offsets,
// 4 bilinear weights with validity folded in. Phase 2 (192 threads = channels):
// 8 points x 4 coalesced gathers with smem-broadcast indices/weights.
__global__ void dcn_sample_kernel(const float* __restrict__ cfs_w, const float* __restrict__ cfs_b,
                                  float* __restrict__ out) {
    int n = blockIdx.x;
    int t = threadIdx.x;
    int bimg = n / (HH*WW);
    int hw = n % (HH*WW);
    int h = hw / WW, w = hw % WW;

    __shared__ float x1s[Csz];
    __shared__ int   sidx[Gsz*Kpts][4];
    __shared__ float swgt[Gsz*Kpts][4];
    __shared__ float smv [Gsz*Kpts];

    x1s[t] = g_x1[n*Csz + t];

    if (t < Gsz*Kpts) {                   // warps 0..2 fully active
        int k = t & 7;
        const float gxA[Kpts] = {-1,-1,-1, 0, 0, 1, 1, 1};
        const float gyA[Kpts] = {-1, 0, 1,-1, 1,-1, 0, 1};
        float ox = g_off[n*Csz + t*2 + 0];
        float oy = g_off[n*Csz + t*2 + 1];
        float px = (float)(w + 1) + gxA[k] + ox;
        float py = (float)(h + 1) + gyA[k] + oy;
        float x0f = floorf(px), y0f = floorf(py);
        float wx = px - x0f, wy = py - y0f;
        int ix0 = (int)x0f, iy0 = (int)y0f;
        #pragma unroll
        for (int cy = 0; cy < 2; cy++) {
            #pragma unroll
            for (int cx = 0; cx < 2; cx++) {
                int iy = iy0 + cy, ix = ix0 + cx;
                bool valid = (iy >= 0 && iy < HP && ix >= 0 && ix < WP);
                int iyc = min(max(iy, 0), HP-1), ixc = min(max(ix, 0), WP-1);
                float wyf = cy ? wy : (1.f - wy);
                float wxf = cx ? wx : (1.f - wx);
                sidx[t][cy*2+cx] = (iyc*WP + ixc)*Csz;
                swgt[t][cy*2+cx] = valid ? wyf*wxf : 0.f;
            }
        }
        // softmax over the 8 points of this group (8 contiguous lanes)
        float m = g_msk[n*(Gsz*Kpts) + t];
        float mx = m;
        #pragma unroll
        for (int o = 1; o < 8; o <<= 1) mx = fmaxf(mx, __shfl_xor_sync(0xffffffffu, mx, o));
        float e = expf(m - mx);
        float ssum = e;
        #pragma unroll
        for (int o = 1; o < 8; o <<= 1) ssum += __shfl_xor_sync(0xffffffffu, ssum, o);
        smv[t] = e / ssum;
    }
    __syncthreads();

    int g = t >> 4, l = t & 15;
    // center feature scale: sigmoid( x1 . cfs_w[g,:] + cfs_b[g] )
    float p = 0.f;
    #pragma unroll
    for (int c = l; c < Csz; c += 16) p += x1s[c] * cfs_w[g*Csz + c];
    #pragma unroll
    for (int o = 8; o; o >>= 1) p += __shfl_xor_sync(0xffffffffu, p, o);
    float cfsv = 1.0f / (1.0f + expf(-(p + cfs_b[g])));

    const float* vb = g_pad + (size_t)bimg*PADSP*Csz + t;   // ch == t
    float acc = 0.f;
    #pragma unroll
    for (int k = 0; k < Kpts; k++) {
        int gk = g*Kpts + k;
        float sval = vb[sidx[gk][0]] * swgt[gk][0]
                   + vb[sidx[gk][1]] * swgt[gk][1]
                   + vb[sidx[gk][2]] * swgt[gk][2]
                   + vb[sidx[gk][3]] * swgt[gk][3];
        acc += smv[gk] * sval;
    }

    float xpv = vb[((h+1)*WP + (w+1))*Csz];
    out[n*Csz + t] = round_tf32(acc*(1.0f - cfsv) + xpv*cfsv);
}

// ---------------- launch ----------------
extern "C" void kernel_launch(void* const* d_in, const int* in_sizes, int n_in,
                              void* d_out, int out_size) {
    const float* x        = (const float*)d_in[0];
    const float* norm1_w  = (const float*)d_in[1];
    const float* norm1_b  = (const float*)d_in[2];
    const float* norm2_w  = (const float*)d_in[3];
    const float* norm2_b  = (const float*)d_in[4];
    const float* rpn1_w   = (const float*)d_in[5];
    const float* rpn1_b   = (const float*)d_in[6];
    const float* rpn2_w   = (const float*)d_in[7];
    const float* rpn2_b   = (const float*)d_in[8];
    const float* in_proj_w= (const float*)d_in[9];
    const float* in_proj_b= (const float*)d_in[10];
    const float* dw_w     = (const float*)d_in[11];
    const float* dw_b     = (const float*)d_in[12];
    const float* dw_ln_w  = (const float*)d_in[13];
    const float* dw_ln_b  = (const float*)d_in[14];
    const float* off_w    = (const float*)d_in[15];
    const float* off_b    = (const float*)d_in[16];
    const float* mask_w   = (const float*)d_in[17];
    const float* mask_b   = (const float*)d_in[18];
    const float* cfs_w    = (const float*)d_in[19];
    const float* cfs_b    = (const float*)d_in[20];
    const float* out_proj_w = (const float*)d_in[21];
    const float* out_proj_b = (const float*)d_in[22];
    const float* fc1_w    = (const float*)d_in[23];
    const float* fc1_b    = (const float*)d_in[24];
    const float* fc2_w    = (const float*)d_in[25];
    const float* fc2_b    = (const float*)d_in[26];
    float* outp = (float*)d_out;

    float *p_dcn, *p_d, *p_x2, *p_t, *p_h1, *p_h2;
    float *p_x1, *p_wom, *p_bom, *p_w2, *p_w3, *p_w4;
    cudaGetSymbolAddress((void**)&p_x1,  g_x1);
    cudaGetSymbolAddress((void**)&p_dcn, g_dcn);
    cudaGetSymbolAddress((void**)&p_d,   g_d);
    cudaGetSymbolAddress((void**)&p_x2,  g_x2);
    cudaGetSymbolAddress((void**)&p_t,   g_t);
    cudaGetSymbolAddress((void**)&p_h1,  g_h1);
    cudaGetSymbolAddress((void**)&p_h2,  g_h2);
    cudaGetSymbolAddress((void**)&p_wom, g_wom);
    cudaGetSymbolAddress((void**)&p_bom, g_bom);
    cudaGetSymbolAddress((void**)&p_w2,  g_w2);
    cudaGetSymbolAddress((void**)&p_w3,  g_w3);
    cudaGetSymbolAddress((void**)&p_w4,  g_w4);

    dim3 thr256(256);
    const int MT = NTOK/128;   // 98 M-tiles

    // 1. LN(x, norm1) + setup (pad border, rounded weights) — one fat launch
    lnsetup_kernel<<<NTOK + SETUP_BLOCKS, Csz>>>(x, norm1_w, norm1_b,
        in_proj_w, off_w, mask_w, out_proj_w, fc1_w, fc2_w, off_b, mask_b);

    // 2. in_proj GEMM (-> padded value buffer)  +  dwconv/LN/GELU — one fat launch
    inproj_dw_kernel<<<GEMM_BLOCKS + DW_BLOCKS, thr256>>>(in_proj_b, dw_w, dw_b,
        dw_ln_w, dw_ln_b);

    // 3. off|mask = x1 @ [off_w|mask_w] + bias   (merged, N=288)
    gemm_tf32_kernel<<<dim3(5, MT), thr256>>>(p_x1, p_wom, p_bom, nullptr, NTOK, NOM, Csz, 0, 2, 0);

    // 4. DCN sampling + cfs (rounded output)
    dcn_sample_kernel<<<NTOK, Csz>>>(cfs_w, cfs_b, p_dcn);

    // 5. d = dcn @ out_proj + b
    gemm_tf32_kernel<<<dim3(3, MT), thr256>>>(p_dcn, p_w2, out_proj_b, p_d, NTOK, Csz, Csz, 0, 0, 0);

    // 6. x2 = x + LN(d, rpn1); t = round(LN(x2, norm2))
    ln_fuse2_kernel<<<NTOK, Csz>>>(p_d, x, rpn1_w, rpn1_b, norm2_w, norm2_b, p_x2, p_t);

    // 7. h1 = round(GELU(t @ fc1 + b))   (N = 768)
    gemm_tf32_kernel<<<dim3(12, MT), thr256>>>(p_t, p_w3, fc1_b, p_h1, NTOK, HID, Csz, 1, 0, 1);

    // 8. h2 = h1 @ fc2 + b   (K = 768)
    gemm_tf32_kernel<<<dim3(3, MT), thr256>>>(p_h1, p_w4, fc2_b, p_h2, NTOK, Csz, HID, 0, 0, 0);

    // 9. out = x2 + LN(h2, rpn2)
    ln_kernel<<<NTOK, Csz>>>(p_h2, p_x2, rpn2_w, rpn2_b, outp, 1e-5f, 0);
}

// round 10
// speedup vs baseline: 1.5231x; 1.5231x over previous
#include <cuda_runtime.h>
#include <cuda_bf16.h>
#include <math.h>

// Problem constants (fixed by the reference)
#define BB   4
#define HH   56
#define WW   56
#define Csz  192
#define Gsz  12
#define CG   16
#define Kpts 8
#define HID  768
#define HP   58
#define WP   58
#define NTOK (BB*HH*WW)          // 12544
#define PADSP (HP*WP)            // 3364
#define NOM  288                  // off(192) + mask(96) concatenated

// ---------------- scratch (device globals; no allocation) ----------------
__device__ float g_xln[NTOK*Csz];
__device__ float g_pad[BB*PADSP*Csz];      // padded value (in_proj output)
__device__ float g_x1 [NTOK*Csz];          // dwconv+LN+GELU (tf32-rounded)
__device__ float g_off[NTOK*Csz];          // G*K*2 = 192
__device__ float g_msk[NTOK*Gsz*Kpts];     // 96 logits
__device__ float g_dcn[NTOK*Csz];          // sampling output (tf32-rounded)
__device__ float g_d  [NTOK*Csz];          // out_proj output
__device__ float g_x2 [NTOK*Csz];          // x + LN(d)
__device__ float g_t  [NTOK*Csz];          // LN(x2, norm2) (tf32-rounded)
__device__ float g_h1 [NTOK*HID];          // (tf32-rounded)
__device__ float g_h2 [NTOK*Csz];
// tf32-rounded weight copies
__device__ float g_w1 [Csz*Csz];           // in_proj
__device__ float g_wom[Csz*NOM];           // off | mask concat
__device__ float g_bom[NOM];               // off_b | mask_b concat
__device__ float g_w2 [Csz*Csz];           // out_proj
__device__ float g_w3 [Csz*HID];           // fc1
__device__ float g_w4 [HID*Csz];           // fc2

// ---------------- helpers ----------------
__device__ __forceinline__ float gelu_exact(float x) {
    return 0.5f * x * (1.0f + erff(x * 0.70710678118654752f));
}

__device__ __forceinline__ float round_tf32(float x) {
    unsigned r;
    asm("cvt.rna.tf32.f32 %0, %1;" : "=r"(r) : "f"(x));
    return __uint_as_float(r);
}

__device__ __forceinline__ unsigned smem_u32(const void* p) {
    return (unsigned)__cvta_generic_to_shared(p);
}

__device__ __forceinline__ void cp_async16(unsigned dst, const void* src, int src_bytes) {
    asm volatile("cp.async.cg.shared.global [%0], [%1], 16, %2;"
                 :: "r"(dst), "l"(src), "r"(src_bytes));
}

// ---------------- setup work sizes ----------------
#define W1_SZ (Csz*Csz)
#define WOM_SZ (Csz*NOM)
#define W3_SZ (Csz*HID)
#define PREP_TOTAL (W1_SZ + WOM_SZ + W1_SZ + W3_SZ + W3_SZ + NOM)
#define BORDER_TOTAL (BB*228*Csz)
#define SETUP_TOTAL (PREP_TOTAL + BORDER_TOTAL)
#define SETUP_BLOCKS 684

__device__ __forceinline__ void setup_work(int i,
        const float* ipw, const float* offw, const float* maskw,
        const float* opw, const float* f1w, const float* f2w,
        const float* offb, const float* maskb) {
    int j = i;
    if (j < BORDER_TOTAL) {
        const int per_img = 228 * Csz;
        int b = j / per_img;
        int r = j % per_img;
        int cell = r / Csz, c = r % Csz;
        int h, w;
        if      (cell < 58)  { h = 0;              w = cell; }
        else if (cell < 116) { h = HP-1;           w = cell - 58; }
        else if (cell < 172) { h = cell - 116 + 1; w = 0; }
        else                 { h = cell - 172 + 1; w = WP-1; }
        g_pad[((size_t)b*PADSP + (size_t)h*WP + w)*Csz + c] = 0.f;
        return;
    }
    j -= BORDER_TOTAL;
    if (j < W1_SZ) { g_w1[j] = round_tf32(ipw[j]); return; }
    j -= W1_SZ;
    if (j < WOM_SZ) {
        int row = j / NOM, col = j % NOM;
        float v = (col < Csz) ? offw[row*(Gsz*Kpts*2) + col] : maskw[row*(Gsz*Kpts) + col - Csz];
        g_wom[j] = round_tf32(v);
        return;
    }
    j -= WOM_SZ;
    if (j < W1_SZ) { g_w2[j] = round_tf32(opw[j]); return; }
    j -= W1_SZ;
    if (j < W3_SZ) { g_w3[j] = round_tf32(f1w[j]); return; }
    j -= W3_SZ;
    if (j < W3_SZ) { g_w4[j] = round_tf32(f2w[j]); return; }
    j -= W3_SZ;
    g_bom[j] = (j < Csz) ? offb[j] : maskb[j - Csz];
}

// ---------------- fat kernel A: LN(x, norm1) -> xln (rounded)  +  setup ----
__global__ void lnsetup_kernel(const float* __restrict__ x,
                               const float* __restrict__ w, const float* __restrict__ b,
                               const float* __restrict__ ipw,
                               const float* __restrict__ offw, const float* __restrict__ maskw,
                               const float* __restrict__ opw,
                               const float* __restrict__ f1w, const float* __restrict__ f2w,
                               const float* __restrict__ offb, const float* __restrict__ maskb) {
    if (blockIdx.x >= NTOK) {
        int base = (blockIdx.x - NTOK) * blockDim.x + threadIdx.x;
        for (int i = base; i < SETUP_TOTAL; i += SETUP_BLOCKS * blockDim.x)
            setup_work(i, ipw, offw, maskw, opw, f1w, f2w, offb, maskb);
        return;
    }
    int n = blockIdx.x;
    int c = threadIdx.x;
    float v = x[n*Csz + c];
    float s = v, s2 = v*v;
    #pragma unroll
    for (int o = 16; o; o >>= 1) {
        s  += __shfl_xor_sync(0xffffffffu, s,  o);
        s2 += __shfl_xor_sync(0xffffffffu, s2, o);
    }
    __shared__ float red[12];
    int wid = c >> 5, lane = c & 31;
    if (lane == 0) { red[wid] = s; red[6+wid] = s2; }
    __syncthreads();
    if (c == 0) {
        float S = 0.f, S2 = 0.f;
        #pragma unroll
        for (int i = 0; i < 6; i++) { S += red[i]; S2 += red[6+i]; }
        red[0] = S; red[6] = S2;
    }
    __syncthreads();
    float mu  = red[0] * (1.0f/Csz);
    float var = red[6] * (1.0f/Csz) - mu*mu;
    g_xln[n*Csz + c] = round_tf32((v - mu) * rsqrtf(var + 1e-5f) * w[c] + b[c]);
}

// ---------------- generic LN kernel: out = LN(in)*w+b (+ res), opt rounding ----
__global__ void ln_kernel(const float* __restrict__ in, const float* __restrict__ res,
                          const float* __restrict__ w, const float* __restrict__ b,
                          float* __restrict__ out, float eps, int rnd) {
    int n = blockIdx.x;
    int c = threadIdx.x;
    float v = in[n*Csz + c];
    float s = v, s2 = v*v;
    #pragma unroll
    for (int o = 16; o; o >>= 1) {
        s  += __shfl_xor_sync(0xffffffffu, s,  o);
        s2 += __shfl_xor_sync(0xffffffffu, s2, o);
    }
    __shared__ float red[12];
    int wid = c >> 5, lane = c & 31;
    if (lane == 0) { red[wid] = s; red[6+wid] = s2; }
    __syncthreads();
    if (c == 0) {
        float S = 0.f, S2 = 0.f;
        #pragma unroll
        for (int i = 0; i < 6; i++) { S += red[i]; S2 += red[6+i]; }
        red[0] = S; red[6] = S2;
    }
    __syncthreads();
    float mu  = red[0] * (1.0f/Csz);
    float var = red[6] * (1.0f/Csz) - mu*mu;
    float o = (v - mu) * rsqrtf(var + eps) * w[c] + b[c];
    if (res) o += res[n*Csz + c];
    if (rnd) o = round_tf32(o);
    out[n*Csz + c] = o;
}

// ---------------- fused: x2 = x + LN(d, rpn1); t = round(LN(x2, norm2)) ----------------
__global__ void ln_fuse2_kernel(const float* __restrict__ d_in, const float* __restrict__ x_in,
                                const float* __restrict__ w1, const float* __restrict__ b1,
                                const float* __restrict__ w2, const float* __restrict__ b2,
                                float* __restrict__ x2_out, float* __restrict__ t_out) {
    int n = blockIdx.x;
    int c = threadIdx.x;
    __shared__ float red[12];
    int wid = c >> 5, lane = c & 31;

    float v = d_in[n*Csz + c];
    float s = v, s2 = v*v;
    #pragma unroll
    for (int o = 16; o; o >>= 1) {
        s  += __shfl_xor_sync(0xffffffffu, s,  o);
        s2 += __shfl_xor_sync(0xffffffffu, s2, o);
    }
    if (lane == 0) { red[wid] = s; red[6+wid] = s2; }
    __syncthreads();
    if (c == 0) {
        float S = 0.f, S2 = 0.f;
        #pragma unroll
        for (int i = 0; i < 6; i++) { S += red[i]; S2 += red[6+i]; }
        red[0] = S; red[6] = S2;
    }
    __syncthreads();
    float mu  = red[0] * (1.0f/Csz);
    float var = red[6] * (1.0f/Csz) - mu*mu;
    float x2 = x_in[n*Csz + c] + (v - mu) * rsqrtf(var + 1e-5f) * w1[c] + b1[c];
    x2_out[n*Csz + c] = x2;
    __syncthreads();   // red[] reuse

    s = x2; s2 = x2*x2;
    #pragma unroll
    for (int o = 16; o; o >>= 1) {
        s  += __shfl_xor_sync(0xffffffffu, s,  o);
        s2 += __shfl_xor_sync(0xffffffffu, s2, o);
    }
    if (lane == 0) { red[wid] = s; red[6+wid] = s2; }
    __syncthreads();
    if (c == 0) {
        float S = 0.f, S2 = 0.f;
        #pragma unroll
        for (int i = 0; i < 6; i++) { S += red[i]; S2 += red[6+i]; }
        red[0] = S; red[6] = S2;
    }
    __syncthreads();
    mu  = red[0] * (1.0f/Csz);
    var = red[6] * (1.0f/Csz) - mu*mu;
    t_out[n*Csz + c] = round_tf32((x2 - mu) * rsqrtf(var + 1e-5f) * w2[c] + b2[c]);
}

// ---------------- GEMM tile body (128x64, 2-stage cp.async, tf32) ----------
#define AS_STRIDE 20
#define BS_STRIDE 72
struct GemmSmem {
    float As[2][128*AS_STRIDE];
    float Bs[2][16*BS_STRIDE];
};

__device__ __forceinline__ void gemm_tile_body(
        GemmSmem* sm, const float* __restrict__ A, const float* __restrict__ W,
        const float* __restrict__ bias, float* __restrict__ C,
        int M, int N, int K, int row0, int col0, int act, int out_mode, int rnd) {
    int tid = threadIdx.x;
    int lane = tid & 31, warp = tid >> 5;
    int gid = lane >> 2, tig = lane & 3;
    int wr = (warp >> 1) * 32;
    int wc = (warp & 1) * 32;

    int a_row = tid >> 1;
    int a_k   = (tid & 1) * 8;
    int b_row = tid >> 4;
    int b_n   = (tid & 15) * 4;

    const float* Abase = A + (size_t)(row0 + a_row)*K + a_k;
    const float* Wbase = W + (size_t)b_row*N + col0 + b_n;
    int b_valid = (col0 + b_n + 4 <= N) ? 16 : 0;

    unsigned as_dst0 = smem_u32(&sm->As[0][a_row*AS_STRIDE + a_k]);
    unsigned as_dst1 = smem_u32(&sm->As[1][a_row*AS_STRIDE + a_k]);
    unsigned bs_dst0 = smem_u32(&sm->Bs[0][b_row*BS_STRIDE + b_n]);
    unsigned bs_dst1 = smem_u32(&sm->Bs[1][b_row*BS_STRIDE + b_n]);

    float acc[2][4][4];
    #pragma unroll
    for (int mi = 0; mi < 2; mi++)
        #pragma unroll
        for (int ni = 0; ni < 4; ni++)
            #pragma unroll
            for (int r = 0; r < 4; r++) acc[mi][ni][r] = 0.f;

    int stages = K / 16;

    cp_async16(as_dst0,      Abase,     16);
    cp_async16(as_dst0 + 16, Abase + 4, 16);
    cp_async16(bs_dst0, Wbase, b_valid);
    asm volatile("cp.async.commit_group;");

    for (int it = 0; it < stages; it++) {
        asm volatile("cp.async.wait_group 0;");
        __syncthreads();

        if (it + 1 < stages) {
            int k0n = (it + 1) * 16;
            const float* An = Abase + k0n;
            const float* Wn = Wbase + (size_t)k0n * N;
            unsigned ad = ((it + 1) & 1) ? as_dst1 : as_dst0;
            unsigned bd = ((it + 1) & 1) ? bs_dst1 : bs_dst0;
            cp_async16(ad,      An,     16);
            cp_async16(ad + 16, An + 4, 16);
            cp_async16(bd, Wn, b_valid);
            asm volatile("cp.async.commit_group;");
        }

        const unsigned* as = (const unsigned*)sm->As[it & 1];
        const unsigned* bs = (const unsigned*)sm->Bs[it & 1];
        #pragma unroll
        for (int ks = 0; ks < 2; ks++) {
            int kb = ks * 8;
            unsigned af[2][4], bf[4][2];
            #pragma unroll
            for (int mi = 0; mi < 2; mi++) {
                int mrow = wr + mi*16 + gid;
                af[mi][0] = as[ mrow   *AS_STRIDE + kb + tig    ];
                af[mi][1] = as[(mrow+8)*AS_STRIDE + kb + tig    ];
                af[mi][2] = as[ mrow   *AS_STRIDE + kb + tig + 4];
                af[mi][3] = as[(mrow+8)*AS_STRIDE + kb + tig + 4];
            }
            #pragma unroll
            for (int ni = 0; ni < 4; ni++) {
                int ncol = wc + ni*8 + gid;
                bf[ni][0] = bs[(kb + tig    )*BS_STRIDE + ncol];
                bf[ni][1] = bs[(kb + tig + 4)*BS_STRIDE + ncol];
            }
            #pragma unroll
            for (int mi = 0; mi < 2; mi++)
                #pragma unroll
                for (int ni = 0; ni < 4; ni++) {
                    asm volatile(
                        "mma.sync.aligned.m16n8k8.row.col.f32.tf32.tf32.f32 "
                        "{%0,%1,%2,%3}, {%4,%5,%6,%7}, {%8,%9}, {%0,%1,%2,%3};"
                        : "+f"(acc[mi][ni][0]), "+f"(acc[mi][ni][1]),
                          "+f"(acc[mi][ni][2]), "+f"(acc[mi][ni][3])
                        : "r"(af[mi][0]), "r"(af[mi][1]), "r"(af[mi][2]), "r"(af[mi][3]),
                          "r"(bf[ni][0]), "r"(bf[ni][1]));
                }
        }
        __syncthreads();
    }

    #pragma unroll
    for (int mi = 0; mi < 2; mi++) {
        #pragma unroll
        for (int ni = 0; ni < 4; ni++) {
            int r0 = row0 + wr + mi*16 + gid;
            int c0 = col0 + wc + ni*8 + 2*tig;
            #pragma unroll
            for (int rr = 0; rr < 2; rr++) {
                int row = r0 + rr*8;
                #pragma unroll
                for (int cc = 0; cc < 2; cc++) {
                    int col = c0 + cc;
                    if (col >= N) continue;
                    float v = acc[mi][ni][rr*2 + cc] + bias[col];
                    if (act == 1) v = gelu_exact(v);
                    if (rnd) v = round_tf32(v);
                    if (out_mode == 1) {
                        int bimg = row / (HH*WW);
                        int hw = row % (HH*WW);
                        int h = hw / WW, w = hw % WW;
                        g_pad[((size_t)bimg*PADSP + (size_t)(h+1)*WP + (w+1))*Csz + col] = v;
                    } else if (out_mode == 2) {
                        if (col < Csz) g_off[(size_t)row*Csz + col] = v;
                        else           g_msk[(size_t)row*(Gsz*Kpts) + col - Csz] = v;
                    } else {
                        C[(size_t)row*N + col] = v;
                    }
                }
            }
        }
    }
}

// ---------------- generic GEMM kernel ----------------
__global__ __launch_bounds__(256) void gemm_tf32_kernel(
        const float* __restrict__ A, const float* __restrict__ W,
        const float* __restrict__ bias, float* __restrict__ C,
        int M, int N, int K, int act, int out_mode, int rnd) {
    __shared__ GemmSmem sm;
    gemm_tile_body(&sm, A, W, bias, C, M, N, K, blockIdx.y*128, blockIdx.x*64,
                   act, out_mode, rnd);
}

// ---------------- fat kernel B: in_proj GEMM + depthwise conv ----------
#define GEMM_BLOCKS (3*(NTOK/128))        // 294
#define DW_BLOCKS   (BB*(HH/4)*WW)        // 3136
__global__ __launch_bounds__(256) void inproj_dw_kernel(
        const float* __restrict__ in_proj_b,
        const float* __restrict__ dww, const float* __restrict__ dwb,
        const float* __restrict__ lnw, const float* __restrict__ lnb) {
    __shared__ GemmSmem sm;   // dw path reuses the first bytes for its reduction
    if (blockIdx.x < GEMM_BLOCKS) {
        int gb = blockIdx.x;
        int col0 = (gb % 3) * 64;
        int row0 = (gb / 3) * 128;
        gemm_tile_body(&sm, g_xln, g_w1, in_proj_b, nullptr, NTOK, Csz, Csz,
                       row0, col0, 0, 1, 0);
        return;
    }
    // ---- dw path: 4 tokens (h0..h0+3, w) ----
    float* redS = (float*)&sm;            // 4*6 sums + 4*6 sqsums = 48 floats
    int blk = blockIdx.x - GEMM_BLOCKS;
    int bimg = blk / ((HH/4)*WW);
    int r = blk % ((HH/4)*WW);
    int h0 = (r / WW) * 4;
    int w = r % WW;
    int c = threadIdx.x;                  // only c < 192 active
    int wid = c >> 5, lane = c & 31;

    float accj[4] = {0.f, 0.f, 0.f, 0.f};
    float s[4], s2[4];
    if (c < Csz) {
        float wt[9];
        #pragma unroll
        for (int i = 0; i < 9; i++) wt[i] = dww[i*Csz + c];
        float vals[6][3];
        #pragma unroll
        for (int rr = 0; rr < 6; rr++) {
            int hh = h0 - 1 + rr;
            #pragma unroll
            for (int cc = 0; cc < 3; cc++) {
                int ww = w - 1 + cc;
                float v = 0.f;
                if (hh >= 0 && hh < HH && ww >= 0 && ww < WW)
                    v = g_xln[((bimg*HH + hh)*WW + ww)*Csz + c];
                vals[rr][cc] = v;
            }
        }
        float bc = dwb[c];
        #pragma unroll
        for (int j = 0; j < 4; j++) {
            float a = 0.f;
            #pragma unroll
            for (int ky = 0; ky < 3; ky++)
                #pragma unroll
                for (int kx = 0; kx < 3; kx++)
                    a += vals[j + ky][kx] * wt[ky*3 + kx];
            accj[j] = a + bc;
        }
        #pragma unroll
        for (int j = 0; j < 4; j++) { s[j] = accj[j]; s2[j] = accj[j]*accj[j]; }
        #pragma unroll
        for (int o = 16; o; o >>= 1) {
            #pragma unroll
            for (int j = 0; j < 4; j++) {
                s[j]  += __shfl_xor_sync(0xffffffffu, s[j],  o);
                s2[j] += __shfl_xor_sync(0xffffffffu, s2[j], o);
            }
        }
        if (lane == 0) {
            #pragma unroll
            for (int j = 0; j < 4; j++) {
                redS[j*6 + wid]      = s[j];
                redS[24 + j*6 + wid] = s2[j];
            }
        }
    }
    __syncthreads();
    if (c < Csz) {
        float lw = lnw[c], lb = lnb[c];
        #pragma unroll
        for (int j = 0; j < 4; j++) {
            float S = 0.f, S2 = 0.f;
            #pragma unroll
            for (int i = 0; i < 6; i++) { S += redS[j*6 + i]; S2 += redS[24 + j*6 + i]; }
            float mu  = S * (1.0f/Csz);
            float var = S2 * (1.0f/Csz) - mu*mu;
            float y = (accj[j] - mu) * rsqrtf(var + 1e-6f) * lw + lb;
            int n = (bimg*HH + h0 + j)*WW + w;
            g_x1[n*Csz + c] = round_tf32(gelu_exact(y));
        }
    }
}

// ---------------- DCNv3 sampling: 2 channels/thread, 2 tokens/block ----------
// 192 threads = 2 tokens x 96 threads; within a token: group g = tt/8,
// lane-in-group l = tt%8, channels g*16 + 2l, 2l+1 (float2).
// Per-thread structure identical to the proven round-7 kernel (predicated
// loads, no LDS in the gather loop) but the per-(g,k) scalar overhead is
// duplicated 8x instead of 16x.
__global__ void dcn_sample_kernel(const float* __restrict__ cfs_w, const float* __restrict__ cfs_b,
                                  float* __restrict__ out) {
    int t = threadIdx.x;
    int tok = t / 96;
    int tt = t % 96;
    int n = blockIdx.x * 2 + tok;
    int g = tt >> 3, l = tt & 7;
    int bimg = n / (HH*WW);
    int hw = n % (HH*WW);
    int h = hw / WW, w = hw % WW;

    __shared__ float x1s[2][Csz];
    x1s[tok][tt]      = g_x1[n*Csz + tt];
    x1s[tok][96 + tt] = g_x1[n*Csz + 96 + tt];
    __syncthreads();

    // center feature scale: sigmoid( x1 . cfs_w[g,:] + cfs_b[g] ), 8 lanes
    const float2* x1v = (const float2*)x1s[tok];
    const float2* cwv = (const float2*)(cfs_w + g*Csz);
    float p = 0.f;
    #pragma unroll
    for (int c = l; c < Csz/2; c += 8) {
        float2 a = x1v[c], b = cwv[c];
        p += a.x*b.x + a.y*b.y;
    }
    #pragma unroll
    for (int o = 4; o; o >>= 1) p += __shfl_xor_sync(0xffffffffu, p, o, 8);
    float cfsv = 1.0f / (1.0f + expf(-(p + cfs_b[g])));

    // softmax over K=8 mask logits (redundant per 8 lanes of a group; cheap)
    float m[Kpts];
    float mx = -1e30f;
    #pragma unroll
    for (int k = 0; k < Kpts; k++) {
        m[k] = g_msk[n*(Gsz*Kpts) + g*Kpts + k];
        mx = fmaxf(mx, m[k]);
    }
    float msum = 0.f;
    #pragma unroll
    for (int k = 0; k < Kpts; k++) { m[k] = expf(m[k] - mx); msum += m[k]; }
    float minv = 1.0f / msum;

    const float gx[Kpts] = {-1,-1,-1, 0, 0, 1, 1, 1};
    const float gy[Kpts] = {-1, 0, 1,-1, 1,-1, 0, 1};
    const float* vb = g_pad + (size_t)bimg*PADSP*Csz;
    int ch = g*CG + 2*l;

    float accx = 0.f, accy = 0.f;
    #pragma unroll
    for (int k = 0; k < Kpts; k++) {
        float ox = g_off[n*Csz + (g*Kpts + k)*2 + 0];
        float oy = g_off[n*Csz + (g*Kpts + k)*2 + 1];
        float px = (float)(w + 1) + gx[k] + ox;
        float py = (float)(h + 1) + gy[k] + oy;
        float x0 = floorf(px), y0 = floorf(py);
        float wx = px - x0, wy = py - y0;
        int ix0 = (int)x0, iy0 = (int)y0;

        float2 s00 = {0.f,0.f}, s01 = {0.f,0.f}, s10 = {0.f,0.f}, s11 = {0.f,0.f};
        if (iy0   >= 0 && iy0   < HP && ix0   >= 0 && ix0   < WP) s00 = *(const float2*)&vb[((size_t)iy0*WP + ix0)*Csz + ch];
        if (iy0   >= 0 && iy0   < HP && ix0+1 >= 0 && ix0+1 < WP) s01 = *(const float2*)&vb[((size_t)iy0*WP + ix0+1)*Csz + ch];
        if (iy0+1 >= 0 && iy0+1 < HP && ix0   >= 0 && ix0   < WP) s10 = *(const float2*)&vb[((size_t)(iy0+1)*WP + ix0)*Csz + ch];
        if (iy0+1 >= 0 && iy0+1 < HP && ix0+1 >= 0 && ix0+1 < WP) s11 = *(const float2*)&vb[((size_t)(iy0+1)*WP + ix0+1)*Csz + ch];

        float w00 = (1.f-wy)*(1.f-wx), w01 = (1.f-wy)*wx;
        float w10 = wy*(1.f-wx),       w11 = wy*wx;
        float svx = s00.x*w00 + s01.x*w01 + s10.x*w10 + s11.x*w11;
        float svy = s00.y*w00 + s01.y*w01 + s10.y*w10 + s11.y*w11;
        float mk = m[k]*minv;
        accx += mk * svx;
        accy += mk * svy;
    }

    float2 xpv = *(const float2*)&vb[((size_t)(h+1)*WP + (w+1))*Csz + ch];
    float2 o;
    o.x = round_tf32(accx*(1.0f - cfsv) + xpv.x*cfsv);
    o.y = round_tf32(accy*(1.0f - cfsv) + xpv.y*cfsv);
    *(float2*)&out[n*Csz + ch] = o;
}

// ---------------- launch ----------------
extern "C" void kernel_launch(void* const* d_in, const int* in_sizes, int n_in,
                              void* d_out, int out_size) {
    const float* x        = (const float*)d_in[0];
    const float* norm1_w  = (const float*)d_in[1];
    const float* norm1_b  = (const float*)d_in[2];
    const float* norm2_w  = (const float*)d_in[3];
    const float* norm2_b  = (const float*)d_in[4];
    const float* rpn1_w   = (const float*)d_in[5];
    const float* rpn1_b   = (const float*)d_in[6];
    const float* rpn2_w   = (const float*)d_in[7];
    const float* rpn2_b   = (const float*)d_in[8];
    const float* in_proj_w= (const float*)d_in[9];
    const float* in_proj_b= (const float*)d_in[10];
    const float* dw_w     = (const float*)d_in[11];
    const float* dw_b     = (const float*)d_in[12];
    const float* dw_ln_w  = (const float*)d_in[13];
    const float* dw_ln_b  = (const float*)d_in[14];
    const float* off_w    = (const float*)d_in[15];
    const float* off_b    = (const float*)d_in[16];
    const float* mask_w   = (const float*)d_in[17];
    const float* mask_b   = (const float*)d_in[18];
    const float* cfs_w    = (const float*)d_in[19];
    const float* cfs_b    = (const float*)d_in[20];
    const float* out_proj_w = (const float*)d_in[21];
    const float* out_proj_b = (const float*)d_in[22];
    const float* fc1_w    = (const float*)d_in[23];
    const float* fc1_b    = (const float*)d_in[24];
    const float* fc2_w    = (const float*)d_in[25];
    const float* fc2_b    = (const float*)d_in[26];
    float* outp = (float*)d_out;

    float *p_dcn, *p_d, *p_x2, *p_t, *p_h1, *p_h2;
    float *p_x1, *p_wom, *p_bom, *p_w2, *p_w3, *p_w4;
    cudaGetSymbolAddress((void**)&p_x1,  g_x1);
    cudaGetSymbolAddress((void**)&p_dcn, g_dcn);
    cudaGetSymbolAddress((void**)&p_d,   g_d);
    cudaGetSymbolAddress((void**)&p_x2,  g_x2);
    cudaGetSymbolAddress((void**)&p_t,   g_t);
    cudaGetSymbolAddress((void**)&p_h1,  g_h1);
    cudaGetSymbolAddress((void**)&p_h2,  g_h2);
    cudaGetSymbolAddress((void**)&p_wom, g_wom);
    cudaGetSymbolAddress((void**)&p_bom, g_bom);
    cudaGetSymbolAddress((void**)&p_w2,  g_w2);
    cudaGetSymbolAddress((void**)&p_w3,  g_w3);
    cudaGetSymbolAddress((void**)&p_w4,  g_w4);

    dim3 thr256(256);
    const int MT = NTOK/128;   // 98 M-tiles

    // 1. LN(x, norm1) + setup (pad border, rounded weights) — one fat launch
    lnsetup_kernel<<<NTOK + SETUP_BLOCKS, Csz>>>(x, norm1_w, norm1_b,
        in_proj_w, off_w, mask_w, out_proj_w, fc1_w, fc2_w, off_b, mask_b);

    // 2. in_proj GEMM (-> padded value buffer)  +  dwconv/LN/GELU — one fat launch
    inproj_dw_kernel<<<GEMM_BLOCKS + DW_BLOCKS, thr256>>>(in_proj_b, dw_w, dw_b,
        dw_ln_w, dw_ln_b);

    // 3. off|mask = x1 @ [off_w|mask_w] + bias   (merged, N=288)
    gemm_tf32_kernel<<<dim3(5, MT), thr256>>>(p_x1, p_wom, p_bom, nullptr, NTOK, NOM, Csz, 0, 2, 0);

    // 4. DCN sampling + cfs (rounded output); 2 tokens per block
    dcn_sample_kernel<<<NTOK/2, Csz>>>(cfs_w, cfs_b, p_dcn);

    // 5. d = dcn @ out_proj + b
    gemm_tf32_kernel<<<dim3(3, MT), thr256>>>(p_dcn, p_w2, out_proj_b, p_d, NTOK, Csz, Csz, 0, 0, 0);

    // 6. x2 = x + LN(d, rpn1); t = round(LN(x2, norm2))
    ln_fuse2_kernel<<<NTOK, Csz>>>(p_d, x, rpn1_w, rpn1_b, norm2_w, norm2_b, p_x2, p_t);

    // 7. h1 = round(GELU(t @ fc1 + b))   (N = 768)
    gemm_tf32_kernel<<<dim3(12, MT), thr256>>>(p_t, p_w3, fc1_b, p_h1, NTOK, HID, Csz, 1, 0, 1);

    // 8. h2 = h1 @ fc2 + b   (K = 768)
    gemm_tf32_kernel<<<dim3(3, MT), thr256>>>(p_h1, p_w4, fc2_b, p_h2, NTOK, Csz, HID, 0, 0, 0);

    // 9. out = x2 + LN(h2, rpn2)
    ln_kernel<<<NTOK, Csz>>>(p_h2, p_x2, rpn2_w, rpn2_b, outp, 1e-5f, 0);
}

// round 11
// speedup vs baseline: 1.5746x; 1.0338x over previous
#include <cuda_runtime.h>
#include <cuda_bf16.h>
#include <math.h>

// Problem constants (fixed by the reference)
#define BB   4
#define HH   56
#define WW   56
#define Csz  192
#define Gsz  12
#define CG   16
#define Kpts 8
#define HID  768
#define HP   58
#define WP   58
#define NTOK (BB*HH*WW)          // 12544
#define PADSP (HP*WP)            // 3364
#define NOM  288                  // off(192) + mask(96) concatenated

// ---------------- scratch (device globals; no allocation) ----------------
__device__ float g_xln[NTOK*Csz];
__device__ float g_pad[BB*PADSP*Csz];      // padded value (in_proj output)
__device__ float g_x1 [NTOK*Csz];          // dwconv+LN+GELU (tf32-rounded)
__device__ float g_off[NTOK*Csz];          // G*K*2 = 192
__device__ float g_msk[NTOK*Gsz*Kpts];     // 96 logits
__device__ float g_dcn[NTOK*Csz];          // sampling output (tf32-rounded)
__device__ float g_d  [NTOK*Csz];          // out_proj output
__device__ float g_x2 [NTOK*Csz];          // x + LN(d)
__device__ float g_t  [NTOK*Csz];          // LN(x2, norm2) (tf32-rounded)
__device__ float g_h1 [NTOK*HID];          // (tf32-rounded)
__device__ float g_h2 [NTOK*Csz];
// tf32-rounded weight copies
__device__ float g_w1 [Csz*Csz];           // in_proj
__device__ float g_wom[Csz*NOM];           // off | mask concat
__device__ float g_bom[NOM];               // off_b | mask_b concat
__device__ float g_w2 [Csz*Csz];           // out_proj
__device__ float g_w3 [Csz*HID];           // fc1
__device__ float g_w4 [HID*Csz];           // fc2

// ---------------- helpers ----------------
__device__ __forceinline__ float gelu_exact(float x) {
    return 0.5f * x * (1.0f + erff(x * 0.70710678118654752f));
}

__device__ __forceinline__ float round_tf32(float x) {
    unsigned r;
    asm("cvt.rna.tf32.f32 %0, %1;" : "=r"(r) : "f"(x));
    return __uint_as_float(r);
}

__device__ __forceinline__ unsigned smem_u32(const void* p) {
    return (unsigned)__cvta_generic_to_shared(p);
}

__device__ __forceinline__ void cp_async16(unsigned dst, const void* src, int src_bytes) {
    asm volatile("cp.async.cg.shared.global [%0], [%1], 16, %2;"
                 :: "r"(dst), "l"(src), "r"(src_bytes));
}

// ---------------- setup work sizes ----------------
#define W1_SZ (Csz*Csz)
#define WOM_SZ (Csz*NOM)
#define W3_SZ (Csz*HID)
#define PREP_TOTAL (W1_SZ + WOM_SZ + W1_SZ + W3_SZ + W3_SZ + NOM)
#define BORDER_TOTAL (BB*228*Csz)
#define SETUP_TOTAL (PREP_TOTAL + BORDER_TOTAL)
#define SETUP_BLOCKS 684

__device__ __forceinline__ void setup_work(int i,
        const float* ipw, const float* offw, const float* maskw,
        const float* opw, const float* f1w, const float* f2w,
        const float* offb, const float* maskb) {
    int j = i;
    if (j < BORDER_TOTAL) {
        const int per_img = 228 * Csz;
        int b = j / per_img;
        int r = j % per_img;
        int cell = r / Csz, c = r % Csz;
        int h, w;
        if      (cell < 58)  { h = 0;              w = cell; }
        else if (cell < 116) { h = HP-1;           w = cell - 58; }
        else if (cell < 172) { h = cell - 116 + 1; w = 0; }
        else                 { h = cell - 172 + 1; w = WP-1; }
        g_pad[((size_t)b*PADSP + (size_t)h*WP + w)*Csz + c] = 0.f;
        return;
    }
    j -= BORDER_TOTAL;
    if (j < W1_SZ) { g_w1[j] = round_tf32(ipw[j]); return; }
    j -= W1_SZ;
    if (j < WOM_SZ) {
        int row = j / NOM, col = j % NOM;
        float v = (col < Csz) ? offw[row*(Gsz*Kpts*2) + col] : maskw[row*(Gsz*Kpts) + col - Csz];
        g_wom[j] = round_tf32(v);
        return;
    }
    j -= WOM_SZ;
    if (j < W1_SZ) { g_w2[j] = round_tf32(opw[j]); return; }
    j -= W1_SZ;
    if (j < W3_SZ) { g_w3[j] = round_tf32(f1w[j]); return; }
    j -= W3_SZ;
    if (j < W3_SZ) { g_w4[j] = round_tf32(f2w[j]); return; }
    j -= W3_SZ;
    g_bom[j] = (j < Csz) ? offb[j] : maskb[j - Csz];
}

// ---------------- fat kernel A: LN(x, norm1) -> xln (rounded)  +  setup ----
__global__ void lnsetup_kernel(const float* __restrict__ x,
                               const float* __restrict__ w, const float* __restrict__ b,
                               const float* __restrict__ ipw,
                               const float* __restrict__ offw, const float* __restrict__ maskw,
                               const float* __restrict__ opw,
                               const float* __restrict__ f1w, const float* __restrict__ f2w,
                               const float* __restrict__ offb, const float* __restrict__ maskb) {
    if (blockIdx.x >= NTOK) {
        int base = (blockIdx.x - NTOK) * blockDim.x + threadIdx.x;
        for (int i = base; i < SETUP_TOTAL; i += SETUP_BLOCKS * blockDim.x)
            setup_work(i, ipw, offw, maskw, opw, f1w, f2w, offb, maskb);
        return;
    }
    int n = blockIdx.x;
    int c = threadIdx.x;
    float v = x[n*Csz + c];
    float s = v, s2 = v*v;
    #pragma unroll
    for (int o = 16; o; o >>= 1) {
        s  += __shfl_xor_sync(0xffffffffu, s,  o);
        s2 += __shfl_xor_sync(0xffffffffu, s2, o);
    }
    __shared__ float red[12];
    int wid = c >> 5, lane = c & 31;
    if (lane == 0) { red[wid] = s; red[6+wid] = s2; }
    __syncthreads();
    if (c == 0) {
        float S = 0.f, S2 = 0.f;
        #pragma unroll
        for (int i = 0; i < 6; i++) { S += red[i]; S2 += red[6+i]; }
        red[0] = S; red[6] = S2;
    }
    __syncthreads();
    float mu  = red[0] * (1.0f/Csz);
    float var = red[6] * (1.0f/Csz) - mu*mu;
    g_xln[n*Csz + c] = round_tf32((v - mu) * rsqrtf(var + 1e-5f) * w[c] + b[c]);
}

// ---------------- generic LN kernel: out = LN(in)*w+b (+ res), opt rounding ----
__global__ void ln_kernel(const float* __restrict__ in, const float* __restrict__ res,
                          const float* __restrict__ w, const float* __restrict__ b,
                          float* __restrict__ out, float eps, int rnd) {
    int n = blockIdx.x;
    int c = threadIdx.x;
    float v = in[n*Csz + c];
    float s = v, s2 = v*v;
    #pragma unroll
    for (int o = 16; o; o >>= 1) {
        s  += __shfl_xor_sync(0xffffffffu, s,  o);
        s2 += __shfl_xor_sync(0xffffffffu, s2, o);
    }
    __shared__ float red[12];
    int wid = c >> 5, lane = c & 31;
    if (lane == 0) { red[wid] = s; red[6+wid] = s2; }
    __syncthreads();
    if (c == 0) {
        float S = 0.f, S2 = 0.f;
        #pragma unroll
        for (int i = 0; i < 6; i++) { S += red[i]; S2 += red[6+i]; }
        red[0] = S; red[6] = S2;
    }
    __syncthreads();
    float mu  = red[0] * (1.0f/Csz);
    float var = red[6] * (1.0f/Csz) - mu*mu;
    float o = (v - mu) * rsqrtf(var + eps) * w[c] + b[c];
    if (res) o += res[n*Csz + c];
    if (rnd) o = round_tf32(o);
    out[n*Csz + c] = o;
}

// ---------------- fused: x2 = x + LN(d, rpn1); t = round(LN(x2, norm2)) ----------------
__global__ void ln_fuse2_kernel(const float* __restrict__ d_in, const float* __restrict__ x_in,
                                const float* __restrict__ w1, const float* __restrict__ b1,
                                const float* __restrict__ w2, const float* __restrict__ b2,
                                float* __restrict__ x2_out, float* __restrict__ t_out) {
    int n = blockIdx.x;
    int c = threadIdx.x;
    __shared__ float red[12];
    int wid = c >> 5, lane = c & 31;

    float v = d_in[n*Csz + c];
    float s = v, s2 = v*v;
    #pragma unroll
    for (int o = 16; o; o >>= 1) {
        s  += __shfl_xor_sync(0xffffffffu, s,  o);
        s2 += __shfl_xor_sync(0xffffffffu, s2, o);
    }
    if (lane == 0) { red[wid] = s; red[6+wid] = s2; }
    __syncthreads();
    if (c == 0) {
        float S = 0.f, S2 = 0.f;
        #pragma unroll
        for (int i = 0; i < 6; i++) { S += red[i]; S2 += red[6+i]; }
        red[0] = S; red[6] = S2;
    }
    __syncthreads();
    float mu  = red[0] * (1.0f/Csz);
    float var = red[6] * (1.0f/Csz) - mu*mu;
    float x2 = x_in[n*Csz + c] + (v - mu) * rsqrtf(var + 1e-5f) * w1[c] + b1[c];
    x2_out[n*Csz + c] = x2;
    __syncthreads();   // red[] reuse

    s = x2; s2 = x2*x2;
    #pragma unroll
    for (int o = 16; o; o >>= 1) {
        s  += __shfl_xor_sync(0xffffffffu, s,  o);
        s2 += __shfl_xor_sync(0xffffffffu, s2, o);
    }
    if (lane == 0) { red[wid] = s; red[6+wid] = s2; }
    __syncthreads();
    if (c == 0) {
        float S = 0.f, S2 = 0.f;
        #pragma unroll
        for (int i = 0; i < 6; i++) { S += red[i]; S2 += red[6+i]; }
        red[0] = S; red[6] = S2;
    }
    __syncthreads();
    mu  = red[0] * (1.0f/Csz);
    var = red[6] * (1.0f/Csz) - mu*mu;
    t_out[n*Csz + c] = round_tf32((x2 - mu) * rsqrtf(var + 1e-5f) * w2[c] + b2[c]);
}

// ---------------- GEMM tile body (128x64, 2-stage cp.async, tf32) ----------
#define AS_STRIDE 20
#define BS_STRIDE 72
struct GemmSmem {
    float As[2][128*AS_STRIDE];
    float Bs[2][16*BS_STRIDE];
};

__device__ __forceinline__ void gemm_tile_body(
        GemmSmem* sm, const float* __restrict__ A, const float* __restrict__ W,
        const float* __restrict__ bias, float* __restrict__ C,
        int M, int N, int K, int row0, int col0, int act, int out_mode, int rnd) {
    int tid = threadIdx.x;
    int lane = tid & 31, warp = tid >> 5;
    int gid = lane >> 2, tig = lane & 3;
    int wr = (warp >> 1) * 32;
    int wc = (warp & 1) * 32;

    int a_row = tid >> 1;
    int a_k   = (tid & 1) * 8;
    int b_row = tid >> 4;
    int b_n   = (tid & 15) * 4;

    const float* Abase = A + (size_t)(row0 + a_row)*K + a_k;
    const float* Wbase = W + (size_t)b_row*N + col0 + b_n;
    int b_valid = (col0 + b_n + 4 <= N) ? 16 : 0;

    unsigned as_dst0 = smem_u32(&sm->As[0][a_row*AS_STRIDE + a_k]);
    unsigned as_dst1 = smem_u32(&sm->As[1][a_row*AS_STRIDE + a_k]);
    unsigned bs_dst0 = smem_u32(&sm->Bs[0][b_row*BS_STRIDE + b_n]);
    unsigned bs_dst1 = smem_u32(&sm->Bs[1][b_row*BS_STRIDE + b_n]);

    float acc[2][4][4];
    #pragma unroll
    for (int mi = 0; mi < 2; mi++)
        #pragma unroll
        for (int ni = 0; ni < 4; ni++)
            #pragma unroll
            for (int r = 0; r < 4; r++) acc[mi][ni][r] = 0.f;

    int stages = K / 16;

    cp_async16(as_dst0,      Abase,     16);
    cp_async16(as_dst0 + 16, Abase + 4, 16);
    cp_async16(bs_dst0, Wbase, b_valid);
    asm volatile("cp.async.commit_group;");

    for (int it = 0; it < stages; it++) {
        asm volatile("cp.async.wait_group 0;");
        __syncthreads();

        if (it + 1 < stages) {
            int k0n = (it + 1) * 16;
            const float* An = Abase + k0n;
            const float* Wn = Wbase + (size_t)k0n * N;
            unsigned ad = ((it + 1) & 1) ? as_dst1 : as_dst0;
            unsigned bd = ((it + 1) & 1) ? bs_dst1 : bs_dst0;
            cp_async16(ad,      An,     16);
            cp_async16(ad + 16, An + 4, 16);
            cp_async16(bd, Wn, b_valid);
            asm volatile("cp.async.commit_group;");
        }

        const unsigned* as = (const unsigned*)sm->As[it & 1];
        const unsigned* bs = (const unsigned*)sm->Bs[it & 1];
        #pragma unroll
        for (int ks = 0; ks < 2; ks++) {
            int kb = ks * 8;
            unsigned af[2][4], bf[4][2];
            #pragma unroll
            for (int mi = 0; mi < 2; mi++) {
                int mrow = wr + mi*16 + gid;
                af[mi][0] = as[ mrow   *AS_STRIDE + kb + tig    ];
                af[mi][1] = as[(mrow+8)*AS_STRIDE + kb + tig    ];
                af[mi][2] = as[ mrow   *AS_STRIDE + kb + tig + 4];
                af[mi][3] = as[(mrow+8)*AS_STRIDE + kb + tig + 4];
            }
            #pragma unroll
            for (int ni = 0; ni < 4; ni++) {
                int ncol = wc + ni*8 + gid;
                bf[ni][0] = bs[(kb + tig    )*BS_STRIDE + ncol];
                bf[ni][1] = bs[(kb + tig + 4)*BS_STRIDE + ncol];
            }
            #pragma unroll
            for (int mi = 0; mi < 2; mi++)
                #pragma unroll
                for (int ni = 0; ni < 4; ni++) {
                    asm volatile(
                        "mma.sync.aligned.m16n8k8.row.col.f32.tf32.tf32.f32 "
                        "{%0,%1,%2,%3}, {%4,%5,%6,%7}, {%8,%9}, {%0,%1,%2,%3};"
                        : "+f"(acc[mi][ni][0]), "+f"(acc[mi][ni][1]),
                          "+f"(acc[mi][ni][2]), "+f"(acc[mi][ni][3])
                        : "r"(af[mi][0]), "r"(af[mi][1]), "r"(af[mi][2]), "r"(af[mi][3]),
                          "r"(bf[ni][0]), "r"(bf[ni][1]));
                }
        }
        __syncthreads();
    }

    #pragma unroll
    for (int mi = 0; mi < 2; mi++) {
        #pragma unroll
        for (int ni = 0; ni < 4; ni++) {
            int r0 = row0 + wr + mi*16 + gid;
            int c0 = col0 + wc + ni*8 + 2*tig;
            #pragma unroll
            for (int rr = 0; rr < 2; rr++) {
                int row = r0 + rr*8;
                #pragma unroll
                for (int cc = 0; cc < 2; cc++) {
                    int col = c0 + cc;
                    if (col >= N) continue;
                    float v = acc[mi][ni][rr*2 + cc] + bias[col];
                    if (act == 1) v = gelu_exact(v);
                    if (rnd) v = round_tf32(v);
                    if (out_mode == 1) {
                        int bimg = row / (HH*WW);
                        int hw = row % (HH*WW);
                        int h = hw / WW, w = hw % WW;
                        g_pad[((size_t)bimg*PADSP + (size_t)(h+1)*WP + (w+1))*Csz + col] = v;
                    } else if (out_mode == 2) {
                        if (col < Csz) g_off[(size_t)row*Csz + col] = v;
                        else           g_msk[(size_t)row*(Gsz*Kpts) + col - Csz] = v;
                    } else {
                        C[(size_t)row*N + col] = v;
                    }
                }
            }
        }
    }
}

// ---------------- generic GEMM kernel ----------------
__global__ __launch_bounds__(256) void gemm_tf32_kernel(
        const float* __restrict__ A, const float* __restrict__ W,
        const float* __restrict__ bias, float* __restrict__ C,
        int M, int N, int K, int act, int out_mode, int rnd) {
    __shared__ GemmSmem sm;
    gemm_tile_body(&sm, A, W, bias, C, M, N, K, blockIdx.y*128, blockIdx.x*64,
                   act, out_mode, rnd);
}

// ---------------- fat kernel B: in_proj GEMM + depthwise conv ----------
#define GEMM_BLOCKS (3*(NTOK/128))        // 294
#define DW_BLOCKS   (BB*(HH/4)*WW)        // 3136
__global__ __launch_bounds__(256) void inproj_dw_kernel(
        const float* __restrict__ in_proj_b,
        const float* __restrict__ dww, const float* __restrict__ dwb,
        const float* __restrict__ lnw, const float* __restrict__ lnb) {
    __shared__ GemmSmem sm;   // dw path reuses the first bytes for its reduction
    if (blockIdx.x < GEMM_BLOCKS) {
        int gb = blockIdx.x;
        int col0 = (gb % 3) * 64;
        int row0 = (gb / 3) * 128;
        gemm_tile_body(&sm, g_xln, g_w1, in_proj_b, nullptr, NTOK, Csz, Csz,
                       row0, col0, 0, 1, 0);
        return;
    }
    // ---- dw path: 4 tokens (h0..h0+3, w) ----
    float* redS = (float*)&sm;            // 4*6 sums + 4*6 sqsums = 48 floats
    int blk = blockIdx.x - GEMM_BLOCKS;
    int bimg = blk / ((HH/4)*WW);
    int r = blk % ((HH/4)*WW);
    int h0 = (r / WW) * 4;
    int w = r % WW;
    int c = threadIdx.x;                  // only c < 192 active
    int wid = c >> 5, lane = c & 31;

    float accj[4] = {0.f, 0.f, 0.f, 0.f};
    float s[4], s2[4];
    if (c < Csz) {
        float wt[9];
        #pragma unroll
        for (int i = 0; i < 9; i++) wt[i] = dww[i*Csz + c];
        float vals[6][3];
        #pragma unroll
        for (int rr = 0; rr < 6; rr++) {
            int hh = h0 - 1 + rr;
            #pragma unroll
            for (int cc = 0; cc < 3; cc++) {
                int ww = w - 1 + cc;
                float v = 0.f;
                if (hh >= 0 && hh < HH && ww >= 0 && ww < WW)
                    v = g_xln[((bimg*HH + hh)*WW + ww)*Csz + c];
                vals[rr][cc] = v;
            }
        }
        float bc = dwb[c];
        #pragma unroll
        for (int j = 0; j < 4; j++) {
            float a = 0.f;
            #pragma unroll
            for (int ky = 0; ky < 3; ky++)
                #pragma unroll
                for (int kx = 0; kx < 3; kx++)
                    a += vals[j + ky][kx] * wt[ky*3 + kx];
            accj[j] = a + bc;
        }
        #pragma unroll
        for (int j = 0; j < 4; j++) { s[j] = accj[j]; s2[j] = accj[j]*accj[j]; }
        #pragma unroll
        for (int o = 16; o; o >>= 1) {
            #pragma unroll
            for (int j = 0; j < 4; j++) {
                s[j]  += __shfl_xor_sync(0xffffffffu, s[j],  o);
                s2[j] += __shfl_xor_sync(0xffffffffu, s2[j], o);
            }
        }
        if (lane == 0) {
            #pragma unroll
            for (int j = 0; j < 4; j++) {
                redS[j*6 + wid]      = s[j];
                redS[24 + j*6 + wid] = s2[j];
            }
        }
    }
    __syncthreads();
    if (c < Csz) {
        float lw = lnw[c], lb = lnb[c];
        #pragma unroll
        for (int j = 0; j < 4; j++) {
            float S = 0.f, S2 = 0.f;
            #pragma unroll
            for (int i = 0; i < 6; i++) { S += redS[j*6 + i]; S2 += redS[24 + j*6 + i]; }
            float mu  = S * (1.0f/Csz);
            float var = S2 * (1.0f/Csz) - mu*mu;
            float y = (accj[j] - mu) * rsqrtf(var + 1e-6f) * lw + lb;
            int n = (bimg*HH + h0 + j)*WW + w;
            g_x1[n*Csz + c] = round_tf32(gelu_exact(y));
        }
    }
}

// ---------------- DCNv3 sampling: 4 channels/thread, 4 tokens/block ----------
// 192 threads = 4 tokens x 48 threads; within a token: group g = tt/4,
// lane-in-group l = tt%4, channels g*16 + 4l .. 4l+3 (float4).
// Same per-thread structure as the proven round-10 kernel (predicated loads,
// no LDS in the gather loop); per-(g,k) scalar overhead duplicated 4x not 8x.
__global__ void dcn_sample_kernel(const float* __restrict__ cfs_w, const float* __restrict__ cfs_b,
                                  float* __restrict__ out) {
    int t = threadIdx.x;
    int tok = t / 48;
    int tt = t % 48;
    int n = blockIdx.x * 4 + tok;
    int g = tt >> 2, l = tt & 3;
    int bimg = n / (HH*WW);
    int hw = n % (HH*WW);
    int h = hw / WW, w = hw % WW;

    __shared__ float4 x1s[4][48];
    x1s[tok][tt] = *(const float4*)&g_x1[n*Csz + tt*4];
    __syncthreads();

    // center feature scale: sigmoid( x1 . cfs_w[g,:] + cfs_b[g] ), 4 lanes
    const float4* cwv = (const float4*)(cfs_w + g*Csz);
    float p = 0.f;
    #pragma unroll
    for (int c = l; c < Csz/4; c += 4) {
        float4 a = x1s[tok][c], b = cwv[c];
        p += a.x*b.x + a.y*b.y + a.z*b.z + a.w*b.w;
    }
    p += __shfl_xor_sync(0xffffffffu, p, 1, 4);
    p += __shfl_xor_sync(0xffffffffu, p, 2, 4);
    float cfsv = 1.0f / (1.0f + expf(-(p + cfs_b[g])));

    // softmax over K=8 mask logits (redundant per 4 lanes of a group; cheap)
    float m[Kpts];
    float mx = -1e30f;
    #pragma unroll
    for (int k = 0; k < Kpts; k++) {
        m[k] = g_msk[n*(Gsz*Kpts) + g*Kpts + k];
        mx = fmaxf(mx, m[k]);
    }
    float msum = 0.f;
    #pragma unroll
    for (int k = 0; k < Kpts; k++) { m[k] = expf(m[k] - mx); msum += m[k]; }
    float minv = 1.0f / msum;

    const float gx[Kpts] = {-1,-1,-1, 0, 0, 1, 1, 1};
    const float gy[Kpts] = {-1, 0, 1,-1, 1,-1, 0, 1};
    const float* vb = g_pad + (size_t)bimg*PADSP*Csz;
    int ch = g*CG + 4*l;

    float ax = 0.f, ay = 0.f, az = 0.f, aw = 0.f;
    #pragma unroll
    for (int k = 0; k < Kpts; k++) {
        float ox = g_off[n*Csz + (g*Kpts + k)*2 + 0];
        float oy = g_off[n*Csz + (g*Kpts + k)*2 + 1];
        float px = (float)(w + 1) + gx[k] + ox;
        float py = (float)(h + 1) + gy[k] + oy;
        float x0 = floorf(px), y0 = floorf(py);
        float wx = px - x0, wy = py - y0;
        int ix0 = (int)x0, iy0 = (int)y0;

        float4 s00 = {0,0,0,0}, s01 = {0,0,0,0}, s10 = {0,0,0,0}, s11 = {0,0,0,0};
        if (iy0   >= 0 && iy0   < HP && ix0   >= 0 && ix0   < WP) s00 = *(const float4*)&vb[((size_t)iy0*WP + ix0)*Csz + ch];
        if (iy0   >= 0 && iy0   < HP && ix0+1 >= 0 && ix0+1 < WP) s01 = *(const float4*)&vb[((size_t)iy0*WP + ix0+1)*Csz + ch];
        if (iy0+1 >= 0 && iy0+1 < HP && ix0   >= 0 && ix0   < WP) s10 = *(const float4*)&vb[((size_t)(iy0+1)*WP + ix0)*Csz + ch];
        if (iy0+1 >= 0 && iy0+1 < HP && ix0+1 >= 0 && ix0+1 < WP) s11 = *(const float4*)&vb[((size_t)(iy0+1)*WP + ix0+1)*Csz + ch];

        float w00 = (1.f-wy)*(1.f-wx), w01 = (1.f-wy)*wx;
        float w10 = wy*(1.f-wx),       w11 = wy*wx;
        float mk = m[k]*minv;
        ax += mk * (s00.x*w00 + s01.x*w01 + s10.x*w10 + s11.x*w11);
        ay += mk * (s00.y*w00 + s01.y*w01 + s10.y*w10 + s11.y*w11);
        az += mk * (s00.z*w00 + s01.z*w01 + s10.z*w10 + s11.z*w11);
        aw += mk * (s00.w*w00 + s01.w*w01 + s10.w*w10 + s11.w*w11);
    }

    float4 xpv = *(const float4*)&vb[((size_t)(h+1)*WP + (w+1))*Csz + ch];
    float4 o;
    o.x = round_tf32(ax*(1.0f - cfsv) + xpv.x*cfsv);
    o.y = round_tf32(ay*(1.0f - cfsv) + xpv.y*cfsv);
    o.z = round_tf32(az*(1.0f - cfsv) + xpv.z*cfsv);
    o.w = round_tf32(aw*(1.0f - cfsv) + xpv.w*cfsv);
    *(float4*)&out[n*Csz + ch] = o;
}

// ---------------- launch ----------------
extern "C" void kernel_launch(void* const* d_in, const int* in_sizes, int n_in,
                              void* d_out, int out_size) {
    const float* x        = (const float*)d_in[0];
    const float* norm1_w  = (const float*)d_in[1];
    const float* norm1_b  = (const float*)d_in[2];
    const float* norm2_w  = (const float*)d_in[3];
    const float* norm2_b  = (const float*)d_in[4];
    const float* rpn1_w   = (const float*)d_in[5];
    const float* rpn1_b   = (const float*)d_in[6];
    const float* rpn2_w   = (const float*)d_in[7];
    const float* rpn2_b   = (const float*)d_in[8];
    const float* in_proj_w= (const float*)d_in[9];
    const float* in_proj_b= (const float*)d_in[10];
    const float* dw_w     = (const float*)d_in[11];
    const float* dw_b     = (const float*)d_in[12];
    const float* dw_ln_w  = (const float*)d_in[13];
    const float* dw_ln_b  = (const float*)d_in[14];
    const float* off_w    = (const float*)d_in[15];
    const float* off_b    = (const float*)d_in[16];
    const float* mask_w   = (const float*)d_in[17];
    const float* mask_b   = (const float*)d_in[18];
    const float* cfs_w    = (const float*)d_in[19];
    const float* cfs_b    = (const float*)d_in[20];
    const float* out_proj_w = (const float*)d_in[21];
    const float* out_proj_b = (const float*)d_in[22];
    const float* fc1_w    = (const float*)d_in[23];
    const float* fc1_b    = (const float*)d_in[24];
    const float* fc2_w    = (const float*)d_in[25];
    const float* fc2_b    = (const float*)d_in[26];
    float* outp = (float*)d_out;

    float *p_dcn, *p_d, *p_x2, *p_t, *p_h1, *p_h2;
    float *p_x1, *p_wom, *p_bom, *p_w2, *p_w3, *p_w4;
    cudaGetSymbolAddress((void**)&p_x1,  g_x1);
    cudaGetSymbolAddress((void**)&p_dcn, g_dcn);
    cudaGetSymbolAddress((void**)&p_d,   g_d);
    cudaGetSymbolAddress((void**)&p_x2,  g_x2);
    cudaGetSymbolAddress((void**)&p_t,   g_t);
    cudaGetSymbolAddress((void**)&p_h1,  g_h1);
    cudaGetSymbolAddress((void**)&p_h2,  g_h2);
    cudaGetSymbolAddress((void**)&p_wom, g_wom);
    cudaGetSymbolAddress((void**)&p_bom, g_bom);
    cudaGetSymbolAddress((void**)&p_w2,  g_w2);
    cudaGetSymbolAddress((void**)&p_w3,  g_w3);
    cudaGetSymbolAddress((void**)&p_w4,  g_w4);

    dim3 thr256(256);
    const int MT = NTOK/128;   // 98 M-tiles

    // 1. LN(x, norm1) + setup (pad border, rounded weights) — one fat launch
    lnsetup_kernel<<<NTOK + SETUP_BLOCKS, Csz>>>(x, norm1_w, norm1_b,
        in_proj_w, off_w, mask_w, out_proj_w, fc1_w, fc2_w, off_b, mask_b);

    // 2. in_proj GEMM (-> padded value buffer)  +  dwconv/LN/GELU — one fat launch
    inproj_dw_kernel<<<GEMM_BLOCKS + DW_BLOCKS, thr256>>>(in_proj_b, dw_w, dw_b,
        dw_ln_w, dw_ln_b);

    // 3. off|mask = x1 @ [off_w|mask_w] + bias   (merged, N=288)
    gemm_tf32_kernel<<<dim3(5, MT), thr256>>>(p_x1, p_wom, p_bom, nullptr, NTOK, NOM, Csz, 0, 2, 0);

    // 4. DCN sampling + cfs (rounded output); 4 tokens per block
    dcn_sample_kernel<<<NTOK/4, Csz>>>(cfs_w, cfs_b, p_dcn);

    // 5. d = dcn @ out_proj + b
    gemm_tf32_kernel<<<dim3(3, MT), thr256>>>(p_dcn, p_w2, out_proj_b, p_d, NTOK, Csz, Csz, 0, 0, 0);

    // 6. x2 = x + LN(d, rpn1); t = round(LN(x2, norm2))
    ln_fuse2_kernel<<<NTOK, Csz>>>(p_d, x, rpn1_w, rpn1_b, norm2_w, norm2_b, p_x2, p_t);

    // 7. h1 = round(GELU(t @ fc1 + b))   (N = 768)
    gemm_tf32_kernel<<<dim3(12, MT), thr256>>>(p_t, p_w3, fc1_b, p_h1, NTOK, HID, Csz, 1, 0, 1);

    // 8. h2 = h1 @ fc2 + b   (K = 768)
    gemm_tf32_kernel<<<dim3(3, MT), thr256>>>(p_h1, p_w4, fc2_b, p_h2, NTOK, Csz, HID, 0, 0, 0);

    // 9. out = x2 + LN(h2, rpn2)
    ln_kernel<<<NTOK, Csz>>>(p_h2, p_x2, rpn2_w, rpn2_b, outp, 1e-5f, 0);
}